// round 3
// baseline (speedup 1.0000x reference)
#include <cuda_runtime.h>
#include <cuda_bf16.h>

// 3D life-like CA step (26-neighbor count, periodic wrap) on a 384^3 float
// grid; output = first out_size (=64) cells of the flattened new grid,
// i.e. cells (x=0, y=0, z=i). Latency-bound tiny kernel: the optimization
// target is the dependent-load chain, not throughput.
//
// Single memory round trip:
//  - 27 independent grid loads per thread (coalesced across z)
//  - rule masks loaded by lanes 0..26 concurrently and packed into 32-bit
//    register bitmasks via __ballot_sync -> final lookup is ALU-only.
//
// Inputs (metadata order):
//   d_in[0] grid         float32 [384^3]
//   d_in[1] survive_mask bool -> int32 [27]
//   d_in[2] birth_mask   bool -> int32 [27]
//   d_in[3] num_models   int32 (unused; out_size gives the count)
// Output: float32 [out_size]

#define DIM 384

__global__ void ca_first_cells_kernel(const float* __restrict__ grid,
                                      const int* __restrict__ survive_mask,
                                      const int* __restrict__ birth_mask,
                                      float* __restrict__ out,
                                      int out_size) {
    int i = blockIdx.x * blockDim.x + threadIdx.x;

    // Fast index math: all outputs have x=0, y=0 when out_size <= DIM
    // (out_size = 64 here). Keep a generic fallback for safety.
    int x, y, z;
    if (out_size <= DIM) {
        x = 0; y = 0; z = i;
    } else {
        z = i % DIM;
        y = (i / DIM) % DIM;
        x = i / (DIM * DIM);
    }

    int zm1 = (z == 0) ? (DIM - 1) : (z - 1);
    int zp1 = (z == DIM - 1) ? 0 : (z + 1);
    int xm1 = (x == 0) ? (DIM - 1) : (x - 1);
    int xp1 = (x == DIM - 1) ? 0 : (x + 1);
    int ym1 = (y == 0) ? (DIM - 1) : (y - 1);
    int yp1 = (y == DIM - 1) ? 0 : (y + 1);

    int xs[3] = {xm1, x, xp1};
    int ys[3] = {ym1, y, yp1};
    int zs[3] = {zm1, z, zp1};

    bool active = (i < out_size);
    // Issue all 27 grid loads up front (independent -> one latency round).
    float v[27];
#pragma unroll
    for (int a = 0; a < 3; a++) {
#pragma unroll
        for (int b = 0; b < 3; b++) {
#pragma unroll
            for (int c = 0; c < 3; c++) {
                int idx = (xs[a] * DIM + ys[b]) * DIM + zs[c];
                v[a * 9 + b * 3 + c] = active ? __ldg(&grid[idx]) : 0.0f;
            }
        }
    }

    // Concurrently: lanes 0..26 fetch the rule tables; pack into bitmasks.
    unsigned lane = threadIdx.x & 31u;
    unsigned mi = lane < 27u ? lane : 26u;
    int sv = survive_mask[mi];
    int bv = birth_mask[mi];
    unsigned sbits = __ballot_sync(0xffffffffu, (sv != 0) && (lane < 27u));
    unsigned bbits = __ballot_sync(0xffffffffu, (bv != 0) && (lane < 27u));

    if (!active) return;

    float s = 0.0f;
#pragma unroll
    for (int t = 0; t < 27; t++) s += v[t];

    float center = v[13];  // (x, y, z) tap
    int ci = (int)(s - center + 0.5f);  // 26-neighbor count, exact for 0/1 grid
    ci = max(0, min(26, ci));

    unsigned bits = (center > 0.5f) ? sbits : bbits;
    out[i] = (float)((bits >> ci) & 1u);
}

extern "C" void kernel_launch(void* const* d_in, const int* in_sizes, int n_in,
                              void* d_out, int out_size) {
    const float* grid = (const float*)d_in[0];
    const int* survive_mask = (const int*)d_in[1];
    const int* birth_mask = (const int*)d_in[2];
    float* out = (float*)d_out;

    int threads = 64;
    int blocks = (out_size + threads - 1) / threads;
    ca_first_cells_kernel<<<blocks, threads>>>(grid, survive_mask, birth_mask, out, out_size);
}

// round 4
// speedup vs baseline: 1.5248x; 1.5248x over previous
#include <cuda_runtime.h>
#include <cuda_bf16.h>

// 3D life-like CA step (26-neighbor count, periodic wrap) on a 384^3 float
// grid; output = first out_size (<=384) cells of the flattened new grid,
// i.e. cells (x=0, y=0, z=i). Latency-bound micro-kernel: one DRAM round
// trip is the floor.
//
//  - mask loads issued first (independent), packed to register bitmasks via
//    one ballot pair -> final rule lookup is ALU-only, no dependent load
//  - 27 independent grid loads per thread, coalesced across z (lanes)
//  - minimal preamble: x=y=0 compile-path only
//
// Inputs: d_in[0] grid f32[384^3], d_in[1] survive int32[27],
//         d_in[2] birth int32[27], d_in[3] num_models (unused)
// Output: float32 [out_size]

#define DIM 384

__global__ __launch_bounds__(DIM, 1)
void ca_first_cells_kernel(const float* __restrict__ grid,
                           const int* __restrict__ survive_mask,
                           const int* __restrict__ birth_mask,
                           float* __restrict__ out,
                           int out_size) {
    const int i = threadIdx.x;           // single block, out_size <= 384
    const unsigned lane = i & 31u;

    // Rule-table loads first: independent of everything, resolve in the same
    // memory round trip as the grid loads.
    const unsigned mi = lane < 27u ? lane : 26u;
    const int sv = survive_mask[mi];
    const int bv = birth_mask[mi];

    // Output cell (0, 0, i): x/y wraps are compile-time constants.
    const int z = i;
    const int zm1 = (z == 0) ? (DIM - 1) : (z - 1);
    const int zp1 = (z == DIM - 1) ? 0 : (z + 1);

    const int xrow[3] = {DIM - 1, 0, 1};   // x-1, x, x+1 (x = 0)
    const int yrow[3] = {DIM - 1, 0, 1};   // y-1, y, y+1 (y = 0)
    const int zcol[3] = {zm1, z, zp1};

    // 27 independent grid loads, front-batched for max MLP.
    float v[27];
#pragma unroll
    for (int a = 0; a < 3; a++) {
        const int xoff = xrow[a] * (DIM * DIM);
#pragma unroll
        for (int b = 0; b < 3; b++) {
            const int xyoff = xoff + yrow[b] * DIM;
#pragma unroll
            for (int c = 0; c < 3; c++) {
                v[a * 9 + b * 3 + c] = __ldg(&grid[xyoff + zcol[c]]);
            }
        }
    }

    // Pack rule tables into register bitmasks (ALU-only lookup below).
    const unsigned valid = (lane < 27u);
    const unsigned sbits = __ballot_sync(0xffffffffu, (sv != 0) & valid);
    const unsigned bbits = __ballot_sync(0xffffffffu, (bv != 0) & valid);

    float s = 0.0f;
#pragma unroll
    for (int t = 0; t < 27; t++) s += v[t];

    const float center = v[13];
    int ci = (int)(s - center + 0.5f);    // exact: grid entries are 0/1
    ci = max(0, min(26, ci));

    const unsigned bits = (center > 0.5f) ? sbits : bbits;
    out[i] = (float)((bits >> ci) & 1u);
}

extern "C" void kernel_launch(void* const* d_in, const int* in_sizes, int n_in,
                              void* d_out, int out_size) {
    const float* grid = (const float*)d_in[0];
    const int* survive_mask = (const int*)d_in[1];
    const int* birth_mask = (const int*)d_in[2];
    float* out = (float*)d_out;

    // out_size = 64 (<= 384): single block of exactly out_size threads.
    ca_first_cells_kernel<<<1, out_size>>>(grid, survive_mask, birth_mask, out, out_size);
}